// round 3
// baseline (speedup 1.0000x reference)
#include <cuda_runtime.h>
#include <math.h>

// ---------------- problem constants ----------------
#define Bn 2
#define Ln 1024
#define HIDn 2048
#define NHn 32
#define HDn 64
#define NKVn 8
#define INTERn 8192
#define DSSMn 2048
#define MHn 32
#define MPn 64
#define MSn 64
#define MKn 4
#define CONV_DIMn (DSSMn + 2*MSn)         // 2176
#define QKV_N (NHn*HDn + 2*NKVn*HDn)      // 3072
#define PROJ_N (2*DSSMn + 2*MSn + MHn)    // 4256
#define TOK (Bn*Ln)                       // 2048

#define KEY_MULT 0.7f
#define ATTN_IN 1.2f
#define ATTN_OUT 0.8f
#define SSM_IN 1.1f
#define SSM_OUT 0.9f
#define GATE_MULT 0.9f
#define DOWN_MULT 0.8f
#define EPSf 1e-5f

// ---------------- scratch (device globals; no allocation) ----------------
__device__ float g_hs[TOK*HIDn];
__device__ float g_qkv[TOK*QKV_N];
__device__ float g_attn[TOK*HIDn];
__device__ float g_attn_h[TOK*HIDn];
__device__ float g_proj[(size_t)TOK*PROJ_N];
__device__ float g_conv[(size_t)TOK*CONV_DIMn];
__device__ float g_dt[TOK*MHn];
__device__ float g_y[TOK*DSSMn];
__device__ float g_ssm_h[TOK*HIDn];
__device__ float g_h[TOK*HIDn];
__device__ float g_h2[TOK*HIDn];
__device__ float g_gu[(size_t)TOK*2*INTERn];
__device__ float g_act[(size_t)TOK*INTERn];

// ---------------- helpers ----------------
__device__ __forceinline__ float block_sum256(float v) {
    __shared__ float sh[8];
    int lane = threadIdx.x & 31;
    int w = threadIdx.x >> 5;
#pragma unroll
    for (int o = 16; o; o >>= 1) v += __shfl_xor_sync(0xffffffffu, v, o);
    if (lane == 0) sh[w] = v;
    __syncthreads();
    if (w == 0) {
        v = (lane < 8) ? sh[lane] : 0.f;
#pragma unroll
        for (int o = 4; o; o >>= 1) v += __shfl_xor_sync(0xffffffffu, v, o);
        if (lane == 0) sh[0] = v;
    }
    __syncthreads();
    return sh[0];
}

// ---------------- RMSNorm: out = x * rsqrt(mean(x^2)+eps) * w ----------------
__global__ __launch_bounds__(256) void rmsnorm_k(const float* __restrict__ x,
                                                 const float* __restrict__ w,
                                                 float* __restrict__ out) {
    int row = blockIdx.x;
    const float4* xr = (const float4*)(x + (size_t)row * HIDn);
    float ss = 0.f;
    for (int i = threadIdx.x; i < HIDn/4; i += 256) {
        float4 v = xr[i];
        ss += v.x*v.x + v.y*v.y + v.z*v.z + v.w*v.w;
    }
    ss = block_sum256(ss);
    float sc = rsqrtf(ss * (1.0f/HIDn) + EPSf);
    float4* orow = (float4*)(out + (size_t)row * HIDn);
    const float4* wr = (const float4*)w;
    for (int i = threadIdx.x; i < HIDn/4; i += 256) {
        float4 v = xr[i]; float4 ww = wr[i];
        v.x *= sc*ww.x; v.y *= sc*ww.y; v.z *= sc*ww.z; v.w *= sc*ww.w;
        orow[i] = v;
    }
}

// ---------------- SGEMM:  C[M,N] = alpha * A[M,K] @ W[N,K]^T (+resid) ----------------
__global__ __launch_bounds__(256) void sgemm_nt(const float* __restrict__ A,
                                                const float* __restrict__ W,
                                                float* __restrict__ C,
                                                const float* __restrict__ resid,
                                                int M, int N, int K, float alpha) {
    const int BM = 128, BN = 128, BK = 8;
    __shared__ float As[BK][BM];
    __shared__ float Ws[BK][BN + 4];
    int tid = threadIdx.x;
    int bm = blockIdx.y * BM, bn = blockIdx.x * BN;
    int lr = tid >> 1;
    int lc = (tid & 1) * 4;
    int tx = tid & 15, ty = tid >> 4;

    float acc[8][8];
#pragma unroll
    for (int i = 0; i < 8; i++)
#pragma unroll
        for (int j = 0; j < 8; j++) acc[i][j] = 0.f;

    const float* Aptr = A + (size_t)(bm + lr) * K + lc;
    int wn = bn + lr;
    bool wvalid = wn < N;
    const float* Wptr = W + (size_t)(wvalid ? wn : 0) * K + lc;

    for (int k0 = 0; k0 < K; k0 += BK) {
        float4 av = *(const float4*)(Aptr + k0);
        float4 wv = wvalid ? *(const float4*)(Wptr + k0) : make_float4(0.f,0.f,0.f,0.f);
        As[lc+0][lr] = av.x; As[lc+1][lr] = av.y; As[lc+2][lr] = av.z; As[lc+3][lr] = av.w;
        Ws[lc+0][lr] = wv.x; Ws[lc+1][lr] = wv.y; Ws[lc+2][lr] = wv.z; Ws[lc+3][lr] = wv.w;
        __syncthreads();
#pragma unroll
        for (int k = 0; k < BK; k++) {
            float a[8], w[8];
            *(float4*)(a)   = *(const float4*)&As[k][ty*8];
            *(float4*)(a+4) = *(const float4*)&As[k][ty*8+4];
            *(float4*)(w)   = *(const float4*)&Ws[k][tx*8];
            *(float4*)(w+4) = *(const float4*)&Ws[k][tx*8+4];
#pragma unroll
            for (int i = 0; i < 8; i++)
#pragma unroll
                for (int j = 0; j < 8; j++) acc[i][j] += a[i] * w[j];
        }
        __syncthreads();
    }
#pragma unroll
    for (int i = 0; i < 8; i++) {
        int mrow = bm + ty*8 + i;
        float* crow = C + (size_t)mrow * N;
        const float* rrow = resid ? (resid + (size_t)mrow * N) : nullptr;
#pragma unroll
        for (int j = 0; j < 8; j++) {
            int n = bn + tx*8 + j;
            if (n < N) {
                float v = alpha * acc[i][j];
                if (rrow) v += rrow[n];
                crow[n] = v;
            }
        }
    }
}

// ---------------- RoPE (+ KEY_MULT for K heads), in-place on g_qkv ----------------
__global__ __launch_bounds__(256) void rope_k(const int* __restrict__ positions) {
    const int NHK = NHn + NKVn; // 40
    int idx = blockIdx.x * blockDim.x + threadIdx.x;
    int total = TOK * NHK * (HDn/2);
    if (idx >= total) return;
    int i = idx & 31;
    int head = (idx >> 5) % NHK;
    int row = idx / (32 * NHK);    // b*L + t
    int t = row % Ln;
    float pos = (float)positions[t];
    // inv = ROPE_BASE^(-(2i)/HD), ln(1e11) = 25.328436022934504
    float inv = expf(-(float)(2*i) * (25.328436022934504f / 64.f));
    float ang = pos * inv;
    float sv, cv;
    sincosf(ang, &sv, &cv);
    float mult = 1.f;
    size_t off;
    if (head < NHn) {
        off = (size_t)row * QKV_N + head * HDn;
    } else {
        off = (size_t)row * QKV_N + NHn*HDn + (head - NHn) * HDn;
        mult = KEY_MULT;
    }
    float x1 = g_qkv[off + i];
    float x2 = g_qkv[off + 32 + i];
    g_qkv[off + i]      = (x1 * cv - x2 * sv) * mult;
    g_qkv[off + 32 + i] = (x2 * cv + x1 * sv) * mult;
}

// ---------------- Flash attention (fp32, causal, GQA) ----------------
__global__ __launch_bounds__(256) void attn_k(const float* __restrict__ qkv,
                                              float* __restrict__ out) {
    const int TQ = 32, TK = 64;
    __shared__ float Qs[TQ][HDn + 1];
    __shared__ float KPs[TK][HDn + 1];
    __shared__ float Vs[TK][HDn];

    int b = blockIdx.y / NHn;
    int h = blockIdx.y % NHn;
    int g = h / (NHn / NKVn);
    int q0 = blockIdx.x * TQ;
    int tid = threadIdx.x, tx = tid & 15, ty = tid >> 4;
    const float* base = qkv + (size_t)(b * Ln) * QKV_N;

    // load Q tile
    for (int i = tid; i < TQ * (HDn/4); i += 256) {
        int r = i >> 4, c = (i & 15) * 4;
        float4 v = *(const float4*)(base + (size_t)(q0 + r) * QKV_N + h * HDn + c);
        Qs[r][c] = v.x; Qs[r][c+1] = v.y; Qs[r][c+2] = v.z; Qs[r][c+3] = v.w;
    }

    float m0 = -1e30f, m1 = -1e30f, l0 = 0.f, l1 = 0.f;
    float o0[4] = {0,0,0,0}, o1[4] = {0,0,0,0};
    int ktiles = (q0 + TQ - 1) / TK + 1;

    for (int kt = 0; kt < ktiles; kt++) {
        int k0 = kt * TK;
        __syncthreads();   // protect KPs(P)/Vs reads of previous iter
        for (int i = tid; i < TK * (HDn/4); i += 256) {
            int r = i >> 4, c = (i & 15) * 4;
            float4 v = *(const float4*)(base + (size_t)(k0 + r) * QKV_N + NHn*HDn + g * HDn + c);
            KPs[r][c] = v.x; KPs[r][c+1] = v.y; KPs[r][c+2] = v.z; KPs[r][c+3] = v.w;
        }
        __syncthreads();

        float s0[4] = {0,0,0,0}, s1[4] = {0,0,0,0};
#pragma unroll 8
        for (int kk = 0; kk < HDn; kk++) {
            float q0v = Qs[ty*2][kk], q1v = Qs[ty*2+1][kk];
#pragma unroll
            for (int j = 0; j < 4; j++) {
                float kv = KPs[tx*4+j][kk];
                s0[j] += q0v * kv;
                s1[j] += q1v * kv;
            }
        }
        const float sc = 0.125f;  // 1/sqrt(64)
        bool needmask = (k0 + TK - 1 > q0);
        int qg0 = q0 + ty*2, qg1 = qg0 + 1;
#pragma unroll
        for (int j = 0; j < 4; j++) {
            s0[j] *= sc; s1[j] *= sc;
            if (needmask) {
                int kg = k0 + tx*4 + j;
                if (kg > qg0) s0[j] = -1e9f;
                if (kg > qg1) s1[j] = -1e9f;
            }
        }
        float tm0 = fmaxf(fmaxf(s0[0], s0[1]), fmaxf(s0[2], s0[3]));
        float tm1 = fmaxf(fmaxf(s1[0], s1[1]), fmaxf(s1[2], s1[3]));
#pragma unroll
        for (int o = 8; o; o >>= 1) {
            tm0 = fmaxf(tm0, __shfl_xor_sync(0xffffffffu, tm0, o));
            tm1 = fmaxf(tm1, __shfl_xor_sync(0xffffffffu, tm1, o));
        }
        float mn0 = fmaxf(m0, tm0), mn1 = fmaxf(m1, tm1);
        float cor0 = __expf(m0 - mn0), cor1 = __expf(m1 - mn1);
        float rs0 = 0.f, rs1 = 0.f;
#pragma unroll
        for (int j = 0; j < 4; j++) {
            s0[j] = __expf(s0[j] - mn0); rs0 += s0[j];
            s1[j] = __expf(s1[j] - mn1); rs1 += s1[j];
        }
#pragma unroll
        for (int o = 8; o; o >>= 1) {
            rs0 += __shfl_xor_sync(0xffffffffu, rs0, o);
            rs1 += __shfl_xor_sync(0xffffffffu, rs1, o);
        }
        l0 = l0 * cor0 + rs0; l1 = l1 * cor1 + rs1;
        m0 = mn0; m1 = mn1;
#pragma unroll
        for (int j = 0; j < 4; j++) { o0[j] *= cor0; o1[j] *= cor1; }

        __syncthreads();  // done reading K
        // write P into KPs, load V
#pragma unroll
        for (int j = 0; j < 4; j++) {
            KPs[ty*2  ][tx*4+j] = s0[j];
            KPs[ty*2+1][tx*4+j] = s1[j];
        }
        for (int i = tid; i < TK * (HDn/4); i += 256) {
            int r = i >> 4, c = (i & 15) * 4;
            float4 v = *(const float4*)(base + (size_t)(k0 + r) * QKV_N + NHn*HDn + NKVn*HDn + g * HDn + c);
            Vs[r][c] = v.x; Vs[r][c+1] = v.y; Vs[r][c+2] = v.z; Vs[r][c+3] = v.w;
        }
        __syncthreads();
#pragma unroll 8
        for (int kk = 0; kk < TK; kk++) {
            float p0 = KPs[ty*2][kk], p1 = KPs[ty*2+1][kk];
#pragma unroll
            for (int j = 0; j < 4; j++) {
                float vv = Vs[kk][tx*4+j];
                o0[j] += p0 * vv;
                o1[j] += p1 * vv;
            }
        }
    }
    float inv0 = 1.f / l0, inv1 = 1.f / l1;
    float4 r0 = make_float4(o0[0]*inv0, o0[1]*inv0, o0[2]*inv0, o0[3]*inv0);
    float4 r1 = make_float4(o1[0]*inv1, o1[1]*inv1, o1[2]*inv1, o1[3]*inv1);
    *(float4*)(out + (size_t)(b*Ln + q0 + ty*2    ) * HIDn + h*HDn + tx*4) = r0;
    *(float4*)(out + (size_t)(b*Ln + q0 + ty*2 + 1) * HIDn + h*HDn + tx*4) = r1;
}

// ---------------- causal conv1d (+mup, +bias, +silu) over xBC ----------------
__global__ __launch_bounds__(256) void conv_k(const float* __restrict__ conv_w,
                                              const float* __restrict__ conv_b) {
    int idx = blockIdx.x * blockDim.x + threadIdx.x;
    if (idx >= Bn*Ln*CONV_DIMn) return;
    int c = idx % CONV_DIMn;
    int t = (idx / CONV_DIMn) % Ln;
    int b = idx / (CONV_DIMn * Ln);
    float mup = (c < DSSMn) ? 0.9f : ((c < DSSMn + MSn) ? 0.8f : 1.1f);
    float4 w = *(const float4*)(conv_w + c*4);
    float wk[4] = {w.x, w.y, w.z, w.w};
    float s = 0.f;
#pragma unroll
    for (int k = 0; k < MKn; k++) {
        int tt = t - (MKn-1) + k;
        if (tt >= 0)
            s += g_proj[(size_t)(b*Ln + tt) * PROJ_N + DSSMn + c] * wk[k];
    }
    float acc = conv_b[c] + mup * s;
    g_conv[idx] = acc / (1.f + __expf(-acc));   // silu
}

// ---------------- dt = softplus(proj_dt * 1.2 + dt_bias) ----------------
__global__ __launch_bounds__(256) void dt_k(const float* __restrict__ dt_bias) {
    int idx = blockIdx.x * blockDim.x + threadIdx.x;
    if (idx >= TOK*MHn) return;
    int h = idx % MHn;
    float v = g_proj[(size_t)(idx / MHn) * PROJ_N + (2*DSSMn + 2*MSn) + h] * 1.2f + dt_bias[h];
    g_dt[idx] = (v > 20.f) ? v : log1pf(__expf(v));
}

// ---------------- selective scan (Mamba2), one block per (b,h) ----------------
__global__ __launch_bounds__(512) void scan_k(const float* __restrict__ A_log,
                                              const float* __restrict__ Dv) {
    int b = blockIdx.x >> 5;       // / MH
    int h = blockIdx.x & 31;
    int tid = threadIdx.x;
    int p = tid >> 3;
    int s0 = (tid & 7) << 3;
    float Ah = -expf(A_log[h]);
    float Dh = Dv[h];
    float st[8] = {0,0,0,0,0,0,0,0};
    for (int t = 0; t < Ln; t++) {
        size_t base = (size_t)(b*Ln + t) * CONV_DIMn;
        float dt = g_dt[(b*Ln + t) * MHn + h];
        float dA = __expf(dt * Ah);
        float xv = g_conv[base + h*MPn + p];
        float4 bv0 = *(const float4*)(g_conv + base + DSSMn + s0);
        float4 bv1 = *(const float4*)(g_conv + base + DSSMn + s0 + 4);
        float4 cv0 = *(const float4*)(g_conv + base + DSSMn + MSn + s0);
        float4 cv1 = *(const float4*)(g_conv + base + DSSMn + MSn + s0 + 4);
        float coef = dt * xv;
        float y = 0.f;
        st[0] = st[0]*dA + coef*bv0.x; y += st[0]*cv0.x;
        st[1] = st[1]*dA + coef*bv0.y; y += st[1]*cv0.y;
        st[2] = st[2]*dA + coef*bv0.z; y += st[2]*cv0.z;
        st[3] = st[3]*dA + coef*bv0.w; y += st[3]*cv0.w;
        st[4] = st[4]*dA + coef*bv1.x; y += st[4]*cv1.x;
        st[5] = st[5]*dA + coef*bv1.y; y += st[5]*cv1.y;
        st[6] = st[6]*dA + coef*bv1.z; y += st[6]*cv1.z;
        st[7] = st[7]*dA + coef*bv1.w; y += st[7]*cv1.w;
        y += __shfl_xor_sync(0xffffffffu, y, 1);
        y += __shfl_xor_sync(0xffffffffu, y, 2);
        y += __shfl_xor_sync(0xffffffffu, y, 4);
        if ((tid & 7) == 0)
            g_y[(size_t)(b*Ln + t) * DSSMn + h*MPn + p] = y + xv * Dh;
    }
}

// ---------------- gate (y * silu(z)) + RMSNorm(ssm_norm_w), in place on g_y ----------------
__global__ __launch_bounds__(256) void gate_rms_k(const float* __restrict__ nw) {
    int row = blockIdx.x;
    const float* zp = g_proj + (size_t)row * PROJ_N;   // z = proj[:, :DSSM], mup=1.0
    float* yp = g_y + (size_t)row * DSSMn;
    float ss = 0.f;
    for (int i = threadIdx.x; i < DSSMn; i += 256) {
        float z = zp[i];
        float gval = yp[i] * (z / (1.f + __expf(-z)));
        yp[i] = gval;
        ss += gval * gval;
    }
    ss = block_sum256(ss);
    float sc = rsqrtf(ss * (1.f/DSSMn) + EPSf);
    for (int i = threadIdx.x; i < DSSMn; i += 256)
        yp[i] = yp[i] * sc * nw[i];
}

// ---------------- combine: h = attn_h + ssm_h + residual (alphas already folded) ----------------
__global__ __launch_bounds__(256) void combine_k(const float* __restrict__ hidden) {
    int idx = blockIdx.x * blockDim.x + threadIdx.x;
    if (idx >= TOK*HIDn/4) return;
    float4 a = ((const float4*)g_attn_h)[idx];
    float4 s = ((const float4*)g_ssm_h)[idx];
    float4 r = ((const float4*)hidden)[idx];
    float4 o;
    o.x = a.x + s.x + r.x; o.y = a.y + s.y + r.y;
    o.z = a.z + s.z + r.z; o.w = a.w + s.w + r.w;
    ((float4*)g_h)[idx] = o;
}

// ---------------- MLP activation: silu(gate*0.9) * up ----------------
__global__ __launch_bounds__(256) void act_k() {
    int idx = blockIdx.x * blockDim.x + threadIdx.x;
    if (idx >= TOK*INTERn) return;
    size_t row = (size_t)(idx / INTERn);
    int j = idx % INTERn;
    float gate = g_gu[row * (2*INTERn) + j] * GATE_MULT;
    float up   = g_gu[row * (2*INTERn) + INTERn + j];
    g_act[idx] = gate / (1.f + __expf(-gate)) * up;
}

// ---------------- host launcher ----------------
static float* sym(const void* s) {
    void* p = nullptr;
    cudaGetSymbolAddress(&p, s);
    return (float*)p;
}

extern "C" void kernel_launch(void* const* d_in, const int* in_sizes, int n_in,
                              void* d_out, int out_size) {
    const float* hidden     = (const float*)d_in[0];
    const int*   positions  = (const int*)  d_in[1];
    const float* w_in_ln    = (const float*)d_in[2];
    const float* qkv_w      = (const float*)d_in[3];
    const float* o_w        = (const float*)d_in[4];
    const float* in_proj_w  = (const float*)d_in[5];
    const float* conv_w     = (const float*)d_in[6];
    const float* conv_b     = (const float*)d_in[7];
    const float* A_log      = (const float*)d_in[8];
    const float* dt_bias    = (const float*)d_in[9];
    const float* Dv         = (const float*)d_in[10];
    const float* ssm_norm_w = (const float*)d_in[11];
    const float* out_proj_w = (const float*)d_in[12];
    const float* w_pre_ff   = (const float*)d_in[13];
    const float* gate_up_w  = (const float*)d_in[14];
    const float* down_w     = (const float*)d_in[15];
    float* out = (float*)d_out;

    float* p_hs     = sym(g_hs);
    float* p_qkv    = sym(g_qkv);
    float* p_attn   = sym(g_attn);
    float* p_attn_h = sym(g_attn_h);
    float* p_proj   = sym(g_proj);
    float* p_y      = sym(g_y);
    float* p_ssm_h  = sym(g_ssm_h);
    float* p_h      = sym(g_h);
    float* p_h2     = sym(g_h2);
    float* p_gu     = sym(g_gu);
    float* p_act    = sym(g_act);

    // 1. input RMSNorm
    rmsnorm_k<<<TOK, 256>>>(hidden, w_in_ln, p_hs);

    // 2. qkv projection (fold ATTN_IN into alpha)
    sgemm_nt<<<dim3(QKV_N/128, TOK/128), 256>>>(p_hs, qkv_w, p_qkv, nullptr,
                                                TOK, QKV_N, HIDn, ATTN_IN);
    // 3. RoPE + key mult
    {
        int total = TOK * (NHn + NKVn) * (HDn/2);
        rope_k<<<(total + 255)/256, 256>>>(positions);
    }
    // 4. attention
    attn_k<<<dim3(Ln/32, Bn*NHn), 256>>>(p_qkv, p_attn);
    // 5. o projection (fold ATTN_OUT)
    sgemm_nt<<<dim3(HIDn/128, TOK/128), 256>>>(p_attn, o_w, p_attn_h, nullptr,
                                               TOK, HIDn, HIDn, ATTN_OUT);

    // 6. SSM in_proj (fold SSM_IN; per-column mup applied downstream)
    sgemm_nt<<<dim3((PROJ_N + 127)/128, TOK/128), 256>>>(p_hs, in_proj_w, p_proj, nullptr,
                                                         TOK, PROJ_N, HIDn, SSM_IN);
    // 7. conv + silu ; dt softplus
    conv_k<<<(Bn*Ln*CONV_DIMn + 255)/256, 256>>>(conv_w, conv_b);
    dt_k<<<(TOK*MHn + 255)/256, 256>>>(dt_bias);
    // 8. selective scan
    scan_k<<<Bn*MHn, 512>>>(A_log, Dv);
    // 9. gate + RMS
    gate_rms_k<<<TOK, 256>>>(ssm_norm_w);
    // 10. out_proj (fold SSM_OUT)
    sgemm_nt<<<dim3(HIDn/128, TOK/128), 256>>>(p_y, out_proj_w, p_ssm_h, nullptr,
                                               TOK, HIDn, DSSMn, SSM_OUT);

    // 11. residual combine + pre-FF RMSNorm
    combine_k<<<(TOK*HIDn/4 + 255)/256, 256>>>(hidden);
    rmsnorm_k<<<TOK, 256>>>(p_h, w_pre_ff, p_h2);

    // 12. MLP
    sgemm_nt<<<dim3((2*INTERn)/128, TOK/128), 256>>>(p_h2, gate_up_w, p_gu, nullptr,
                                                     TOK, 2*INTERn, HIDn, 1.0f);
    act_k<<<(TOK*INTERn + 255)/256, 256>>>();
    sgemm_nt<<<dim3(HIDn/128, TOK/128), 256>>>(p_act, down_w, out, p_h,
                                               TOK, HIDn, INTERn, DOWN_MULT);
}

// round 9
// speedup vs baseline: 2.4072x; 2.4072x over previous
#include <cuda_runtime.h>
#include <math.h>
#include <stdint.h>

// ---------------- problem constants ----------------
#define Bn 2
#define Ln 1024
#define HIDn 2048
#define NHn 32
#define HDn 64
#define NKVn 8
#define INTERn 8192
#define DSSMn 2048
#define MHn 32
#define MPn 64
#define MSn 64
#define MKn 4
#define CONV_DIMn (DSSMn + 2*MSn)         // 2176
#define QKV_N (NHn*HDn + 2*NKVn*HDn)      // 3072
#define PROJ_N (2*DSSMn + 2*MSn + MHn)    // 4256
#define TOK (Bn*Ln)                       // 2048

#define KEY_MULT 0.7f
#define ATTN_IN 1.2f
#define ATTN_OUT 0.8f
#define SSM_IN 1.1f
#define SSM_OUT 0.9f
#define GATE_MULT 0.9f
#define DOWN_MULT 0.8f
#define EPSf 1e-5f

// ---------------- scratch (device globals; no allocation) ----------------
__device__ float g_hs[TOK*HIDn];
__device__ float g_qkv[TOK*QKV_N];
__device__ float g_attn[TOK*HIDn];
__device__ float g_attn_h[TOK*HIDn];
__device__ float g_proj[(size_t)TOK*PROJ_N];
__device__ float g_conv[(size_t)TOK*CONV_DIMn];
__device__ float g_dt[TOK*MHn];
__device__ float g_y[TOK*DSSMn];
__device__ float g_ssm_h[TOK*HIDn];
__device__ float g_h[TOK*HIDn];
__device__ float g_h2[TOK*HIDn];
__device__ float g_gu[(size_t)TOK*2*INTERn];
__device__ float g_act[(size_t)TOK*INTERn];
// tf32-rounded weight copies
__device__ float g_wqkv[(size_t)QKV_N*HIDn];
__device__ float g_wo[(size_t)HIDn*HIDn];
__device__ float g_win[(size_t)PROJ_N*HIDn];
__device__ float g_wout[(size_t)HIDn*DSSMn];
__device__ float g_wgu[(size_t)2*INTERn*HIDn];
__device__ float g_wdn[(size_t)HIDn*INTERn];

// ---------------- helpers ----------------
__device__ __forceinline__ float tf32r(float x) {
    uint32_t u;
    asm("cvt.rna.tf32.f32 %0, %1;" : "=r"(u) : "f"(x));
    return __uint_as_float(u);
}

__device__ __forceinline__ float block_sum256(float v) {
    __shared__ float sh[8];
    int lane = threadIdx.x & 31;
    int w = threadIdx.x >> 5;
#pragma unroll
    for (int o = 16; o; o >>= 1) v += __shfl_xor_sync(0xffffffffu, v, o);
    if (lane == 0) sh[w] = v;
    __syncthreads();
    if (w == 0) {
        v = (lane < 8) ? sh[lane] : 0.f;
#pragma unroll
        for (int o = 4; o; o >>= 1) v += __shfl_xor_sync(0xffffffffu, v, o);
        if (lane == 0) sh[0] = v;
    }
    __syncthreads();
    return sh[0];
}

// ---------------- weight -> tf32-rounded copy ----------------
__global__ __launch_bounds__(256) void cvtw_k(const float* __restrict__ in,
                                              float* __restrict__ out, int n4) {
    int i = blockIdx.x * blockDim.x + threadIdx.x;
    if (i >= n4) return;
    float4 v = ((const float4*)in)[i];
    v.x = tf32r(v.x); v.y = tf32r(v.y); v.z = tf32r(v.z); v.w = tf32r(v.w);
    ((float4*)out)[i] = v;
}

// ---------------- RMSNorm (output tf32-rounded: feeds GEMM A) ----------------
__global__ __launch_bounds__(256) void rmsnorm_k(const float* __restrict__ x,
                                                 const float* __restrict__ w,
                                                 float* __restrict__ out) {
    int row = blockIdx.x;
    const float4* xr = (const float4*)(x + (size_t)row * HIDn);
    float ss = 0.f;
    for (int i = threadIdx.x; i < HIDn/4; i += 256) {
        float4 v = xr[i];
        ss += v.x*v.x + v.y*v.y + v.z*v.z + v.w*v.w;
    }
    ss = block_sum256(ss);
    float sc = rsqrtf(ss * (1.0f/HIDn) + EPSf);
    float4* orow = (float4*)(out + (size_t)row * HIDn);
    const float4* wr = (const float4*)w;
    for (int i = threadIdx.x; i < HIDn/4; i += 256) {
        float4 v = xr[i]; float4 ww = wr[i];
        v.x = tf32r(v.x*sc*ww.x); v.y = tf32r(v.y*sc*ww.y);
        v.z = tf32r(v.z*sc*ww.z); v.w = tf32r(v.w*sc*ww.w);
        orow[i] = v;
    }
}

// ---------------- TF32 tensor-core GEMM ----------------
// C[M,N] = alpha * A[M,K] @ W[N,K]^T (+resid). A,W must be tf32-pre-rounded.
// 128x128x16 tile, 256 threads, 8 warps (2x4), warp tile 64x32, mma m16n8k8.
#define GSTR 20   // smem row stride (floats): 16 + 4 -> conflict-free frags

__device__ __forceinline__ void cpa16(uint32_t dst, const float* src, int bytes) {
    asm volatile("cp.async.ca.shared.global [%0], [%1], 16, %2;"
                 :: "r"(dst), "l"(src), "r"(bytes));
}

__global__ __launch_bounds__(256, 2) void tgemm_nt(const float* __restrict__ A,
                                                   const float* __restrict__ W,
                                                   float* __restrict__ C,
                                                   const float* __restrict__ resid,
                                                   int M, int N, int K, float alpha) {
    __shared__ float As[2][128*GSTR];
    __shared__ float Ws[2][128*GSTR];

    int tid = threadIdx.x;
    int bm = blockIdx.y * 128, bn = blockIdx.x * 128;
    int lane = tid & 31, wid = tid >> 5;
    int g = lane >> 2, t = lane & 3;
    int wm = wid & 1, wn_ = wid >> 1;

    // global->smem load assignment: 2 threads per row, 2 float4 each
    int lr = tid >> 1;
    int lk = (tid & 1) * 8;
    const float* Ag = A + (size_t)(bm + lr) * K + lk;
    int wrow = bn + lr;
    const float* Wg = W + (size_t)(wrow < N ? wrow : N-1) * K + lk;
    int wbytes = (wrow < N) ? 16 : 0;
    uint32_t sA = (uint32_t)__cvta_generic_to_shared(&As[0][0]) + (lr*GSTR + lk)*4;
    uint32_t sW = (uint32_t)__cvta_generic_to_shared(&Ws[0][0]) + (lr*GSTR + lk)*4;
    const uint32_t bufB = 128*GSTR*4;

    float acc[4][4][4];
#pragma unroll
    for (int i = 0; i < 4; i++)
#pragma unroll
        for (int j = 0; j < 4; j++)
#pragma unroll
            for (int e = 0; e < 4; e++) acc[i][j][e] = 0.f;

    int nk = K / 16;
    // prologue: stage 0
    cpa16(sA, Ag, 16); cpa16(sA+16, Ag+4, 16);
    cpa16(sW, Wg, wbytes); cpa16(sW+16, Wg+4, wbytes);
    asm volatile("cp.async.commit_group;");

    for (int kb = 0; kb < nk; kb++) {
        if (kb + 1 < nk) {
            uint32_t o = ((kb+1)&1) * bufB;
            const float* a2 = Ag + (kb+1)*16;
            const float* w2 = Wg + (kb+1)*16;
            cpa16(sA+o, a2, 16); cpa16(sA+o+16, a2+4, 16);
            cpa16(sW+o, w2, wbytes); cpa16(sW+o+16, w2+4, wbytes);
        }
        asm volatile("cp.async.commit_group;");
        asm volatile("cp.async.wait_group 1;");
        __syncthreads();

        const float* ab = &As[kb&1][0] + (wm*64 + g)*GSTR + t;
        const float* bb = &Ws[kb&1][0] + (wn_*32 + g)*GSTR + t;
#pragma unroll
        for (int kk = 0; kk < 16; kk += 8) {
            uint32_t af[4][4], bf[4][2];
#pragma unroll
            for (int mi = 0; mi < 4; mi++) {
                af[mi][0] = __float_as_uint(ab[mi*(16*GSTR) + kk]);
                af[mi][1] = __float_as_uint(ab[mi*(16*GSTR) + 8*GSTR + kk]);
                af[mi][2] = __float_as_uint(ab[mi*(16*GSTR) + kk + 4]);
                af[mi][3] = __float_as_uint(ab[mi*(16*GSTR) + 8*GSTR + kk + 4]);
            }
#pragma unroll
            for (int ni = 0; ni < 4; ni++) {
                bf[ni][0] = __float_as_uint(bb[ni*(8*GSTR) + kk]);
                bf[ni][1] = __float_as_uint(bb[ni*(8*GSTR) + kk + 4]);
            }
#pragma unroll
            for (int mi = 0; mi < 4; mi++)
#pragma unroll
                for (int ni = 0; ni < 4; ni++) {
                    asm volatile(
                        "mma.sync.aligned.m16n8k8.row.col.f32.tf32.tf32.f32 "
                        "{%0,%1,%2,%3}, {%4,%5,%6,%7}, {%8,%9}, {%0,%1,%2,%3};"
                        : "+f"(acc[mi][ni][0]), "+f"(acc[mi][ni][1]),
                          "+f"(acc[mi][ni][2]), "+f"(acc[mi][ni][3])
                        : "r"(af[mi][0]), "r"(af[mi][1]), "r"(af[mi][2]), "r"(af[mi][3]),
                          "r"(bf[ni][0]), "r"(bf[ni][1]));
                }
        }
        __syncthreads();
    }

    // epilogue
#pragma unroll
    for (int mi = 0; mi < 4; mi++) {
        int r0 = bm + wm*64 + mi*16 + g;
        float* c0 = C + (size_t)r0 * N;
        float* c1 = C + (size_t)(r0+8) * N;
        const float* rr0 = resid ? resid + (size_t)r0 * N : nullptr;
        const float* rr1 = resid ? resid + (size_t)(r0+8) * N : nullptr;
#pragma unroll
        for (int ni = 0; ni < 4; ni++) {
            int cc = bn + wn_*32 + ni*8 + t*2;
            if (cc < N) {
                float2 v0 = make_float2(alpha*acc[mi][ni][0], alpha*acc[mi][ni][1]);
                float2 v1 = make_float2(alpha*acc[mi][ni][2], alpha*acc[mi][ni][3]);
                if (rr0) {
                    v0.x += rr0[cc]; v0.y += rr0[cc+1];
                    v1.x += rr1[cc]; v1.y += rr1[cc+1];
                }
                *(float2*)(c0 + cc) = v0;
                *(float2*)(c1 + cc) = v1;
            }
        }
    }
}

// ---------------- RoPE (+ KEY_MULT for K heads), in-place on g_qkv ----------------
__global__ __launch_bounds__(256) void rope_k(const int* __restrict__ positions) {
    const int NHK = NHn + NKVn; // 40
    int idx = blockIdx.x * blockDim.x + threadIdx.x;
    int total = TOK * NHK * (HDn/2);
    if (idx >= total) return;
    int i = idx & 31;
    int head = (idx >> 5) % NHK;
    int row = idx / (32 * NHK);    // b*L + t
    int t = row % Ln;
    float pos = (float)positions[t];
    float inv = expf(-(float)(2*i) * (25.328436022934504f / 64.f));
    float ang = pos * inv;
    float sv, cv;
    sincosf(ang, &sv, &cv);
    float mult = 1.f;
    size_t off;
    if (head < NHn) {
        off = (size_t)row * QKV_N + head * HDn;
    } else {
        off = (size_t)row * QKV_N + NHn*HDn + (head - NHn) * HDn;
        mult = KEY_MULT;
    }
    float x1 = g_qkv[off + i];
    float x2 = g_qkv[off + 32 + i];
    g_qkv[off + i]      = (x1 * cv - x2 * sv) * mult;
    g_qkv[off + 32 + i] = (x2 * cv + x1 * sv) * mult;
}

// ---------------- Flash attention (fp32, causal, GQA); out tf32-rounded ----------------
__global__ __launch_bounds__(256) void attn_k(const float* __restrict__ qkv,
                                              float* __restrict__ out) {
    const int TQ = 32, TK = 64;
    __shared__ float Qs[TQ][HDn + 1];
    __shared__ float KPs[TK][HDn + 1];
    __shared__ float Vs[TK][HDn];

    int b = blockIdx.y / NHn;
    int h = blockIdx.y % NHn;
    int g = h / (NHn / NKVn);
    int q0 = blockIdx.x * TQ;
    int tid = threadIdx.x, tx = tid & 15, ty = tid >> 4;
    const float* base = qkv + (size_t)(b * Ln) * QKV_N;

    for (int i = tid; i < TQ * (HDn/4); i += 256) {
        int r = i >> 4, c = (i & 15) * 4;
        float4 v = *(const float4*)(base + (size_t)(q0 + r) * QKV_N + h * HDn + c);
        Qs[r][c] = v.x; Qs[r][c+1] = v.y; Qs[r][c+2] = v.z; Qs[r][c+3] = v.w;
    }

    float m0 = -1e30f, m1 = -1e30f, l0 = 0.f, l1 = 0.f;
    float o0[4] = {0,0,0,0}, o1[4] = {0,0,0,0};
    int ktiles = (q0 + TQ - 1) / TK + 1;

    for (int kt = 0; kt < ktiles; kt++) {
        int k0 = kt * TK;
        __syncthreads();
        for (int i = tid; i < TK * (HDn/4); i += 256) {
            int r = i >> 4, c = (i & 15) * 4;
            float4 v = *(const float4*)(base + (size_t)(k0 + r) * QKV_N + NHn*HDn + g * HDn + c);
            KPs[r][c] = v.x; KPs[r][c+1] = v.y; KPs[r][c+2] = v.z; KPs[r][c+3] = v.w;
        }
        __syncthreads();

        float s0[4] = {0,0,0,0}, s1[4] = {0,0,0,0};
#pragma unroll 8
        for (int kk = 0; kk < HDn; kk++) {
            float q0v = Qs[ty*2][kk], q1v = Qs[ty*2+1][kk];
#pragma unroll
            for (int j = 0; j < 4; j++) {
                float kv = KPs[tx*4+j][kk];
                s0[j] += q0v * kv;
                s1[j] += q1v * kv;
            }
        }
        const float sc = 0.125f;
        bool needmask = (k0 + TK - 1 > q0);
        int qg0 = q0 + ty*2, qg1 = qg0 + 1;
#pragma unroll
        for (int j = 0; j < 4; j++) {
            s0[j] *= sc; s1[j] *= sc;
            if (needmask) {
                int kg = k0 + tx*4 + j;
                if (kg > qg0) s0[j] = -1e9f;
                if (kg > qg1) s1[j] = -1e9f;
            }
        }
        float tm0 = fmaxf(fmaxf(s0[0], s0[1]), fmaxf(s0[2], s0[3]));
        float tm1 = fmaxf(fmaxf(s1[0], s1[1]), fmaxf(s1[2], s1[3]));
#pragma unroll
        for (int o = 8; o; o >>= 1) {
            tm0 = fmaxf(tm0, __shfl_xor_sync(0xffffffffu, tm0, o));
            tm1 = fmaxf(tm1, __shfl_xor_sync(0xffffffffu, tm1, o));
        }
        float mn0 = fmaxf(m0, tm0), mn1 = fmaxf(m1, tm1);
        float cor0 = __expf(m0 - mn0), cor1 = __expf(m1 - mn1);
        float rs0 = 0.f, rs1 = 0.f;
#pragma unroll
        for (int j = 0; j < 4; j++) {
            s0[j] = __expf(s0[j] - mn0); rs0 += s0[j];
            s1[j] = __expf(s1[j] - mn1); rs1 += s1[j];
        }
#pragma unroll
        for (int o = 8; o; o >>= 1) {
            rs0 += __shfl_xor_sync(0xffffffffu, rs0, o);
            rs1 += __shfl_xor_sync(0xffffffffu, rs1, o);
        }
        l0 = l0 * cor0 + rs0; l1 = l1 * cor1 + rs1;
        m0 = mn0; m1 = mn1;
#pragma unroll
        for (int j = 0; j < 4; j++) { o0[j] *= cor0; o1[j] *= cor1; }

        __syncthreads();
#pragma unroll
        for (int j = 0; j < 4; j++) {
            KPs[ty*2  ][tx*4+j] = s0[j];
            KPs[ty*2+1][tx*4+j] = s1[j];
        }
        for (int i = tid; i < TK * (HDn/4); i += 256) {
            int r = i >> 4, c = (i & 15) * 4;
            float4 v = *(const float4*)(base + (size_t)(k0 + r) * QKV_N + NHn*HDn + NKVn*HDn + g * HDn + c);
            Vs[r][c] = v.x; Vs[r][c+1] = v.y; Vs[r][c+2] = v.z; Vs[r][c+3] = v.w;
        }
        __syncthreads();
#pragma unroll 8
        for (int kk = 0; kk < TK; kk++) {
            float p0 = KPs[ty*2][kk], p1 = KPs[ty*2+1][kk];
#pragma unroll
            for (int j = 0; j < 4; j++) {
                float vv = Vs[kk][tx*4+j];
                o0[j] += p0 * vv;
                o1[j] += p1 * vv;
            }
        }
    }
    float inv0 = 1.f / l0, inv1 = 1.f / l1;
    float4 r0 = make_float4(tf32r(o0[0]*inv0), tf32r(o0[1]*inv0), tf32r(o0[2]*inv0), tf32r(o0[3]*inv0));
    float4 r1 = make_float4(tf32r(o1[0]*inv1), tf32r(o1[1]*inv1), tf32r(o1[2]*inv1), tf32r(o1[3]*inv1));
    *(float4*)(out + (size_t)(b*Ln + q0 + ty*2    ) * HIDn + h*HDn + tx*4) = r0;
    *(float4*)(out + (size_t)(b*Ln + q0 + ty*2 + 1) * HIDn + h*HDn + tx*4) = r1;
}

// ---------------- causal conv1d (+mup, +bias, +silu) over xBC ----------------
__global__ __launch_bounds__(256) void conv_k(const float* __restrict__ conv_w,
                                              const float* __restrict__ conv_b) {
    int idx = blockIdx.x * blockDim.x + threadIdx.x;
    if (idx >= Bn*Ln*CONV_DIMn) return;
    int c = idx % CONV_DIMn;
    int t = (idx / CONV_DIMn) % Ln;
    int b = idx / (CONV_DIMn * Ln);
    float mup = (c < DSSMn) ? 0.9f : ((c < DSSMn + MSn) ? 0.8f : 1.1f);
    float4 w = *(const float4*)(conv_w + c*4);
    float wk[4] = {w.x, w.y, w.z, w.w};
    float s = 0.f;
#pragma unroll
    for (int k = 0; k < MKn; k++) {
        int tt = t - (MKn-1) + k;
        if (tt >= 0)
            s += g_proj[(size_t)(b*Ln + tt) * PROJ_N + DSSMn + c] * wk[k];
    }
    float acc = conv_b[c] + mup * s;
    g_conv[idx] = acc / (1.f + __expf(-acc));
}

// ---------------- dt = softplus(proj_dt * 1.2 + dt_bias) ----------------
__global__ __launch_bounds__(256) void dt_k(const float* __restrict__ dt_bias) {
    int idx = blockIdx.x * blockDim.x + threadIdx.x;
    if (idx >= TOK*MHn) return;
    int h = idx % MHn;
    float v = g_proj[(size_t)(idx / MHn) * PROJ_N + (2*DSSMn + 2*MSn) + h] * 1.2f + dt_bias[h];
    g_dt[idx] = (v > 20.f) ? v : log1pf(__expf(v));
}

// ---------------- selective scan (Mamba2), one block per (b,h) ----------------
__global__ __launch_bounds__(512) void scan_k(const float* __restrict__ A_log,
                                              const float* __restrict__ Dv) {
    int b = blockIdx.x >> 5;
    int h = blockIdx.x & 31;
    int tid = threadIdx.x;
    int p = tid >> 3;
    int s0 = (tid & 7) << 3;
    float Ah = -expf(A_log[h]);
    float Dh = Dv[h];
    float st[8] = {0,0,0,0,0,0,0,0};
    for (int t = 0; t < Ln; t++) {
        size_t base = (size_t)(b*Ln + t) * CONV_DIMn;
        float dt = g_dt[(b*Ln + t) * MHn + h];
        float dA = __expf(dt * Ah);
        float xv = g_conv[base + h*MPn + p];
        float4 bv0 = *(const float4*)(g_conv + base + DSSMn + s0);
        float4 bv1 = *(const float4*)(g_conv + base + DSSMn + s0 + 4);
        float4 cv0 = *(const float4*)(g_conv + base + DSSMn + MSn + s0);
        float4 cv1 = *(const float4*)(g_conv + base + DSSMn + MSn + s0 + 4);
        float coef = dt * xv;
        float y = 0.f;
        st[0] = st[0]*dA + coef*bv0.x; y += st[0]*cv0.x;
        st[1] = st[1]*dA + coef*bv0.y; y += st[1]*cv0.y;
        st[2] = st[2]*dA + coef*bv0.z; y += st[2]*cv0.z;
        st[3] = st[3]*dA + coef*bv0.w; y += st[3]*cv0.w;
        st[4] = st[4]*dA + coef*bv1.x; y += st[4]*cv1.x;
        st[5] = st[5]*dA + coef*bv1.y; y += st[5]*cv1.y;
        st[6] = st[6]*dA + coef*bv1.z; y += st[6]*cv1.z;
        st[7] = st[7]*dA + coef*bv1.w; y += st[7]*cv1.w;
        y += __shfl_xor_sync(0xffffffffu, y, 1);
        y += __shfl_xor_sync(0xffffffffu, y, 2);
        y += __shfl_xor_sync(0xffffffffu, y, 4);
        if ((tid & 7) == 0)
            g_y[(size_t)(b*Ln + t) * DSSMn + h*MPn + p] = y + xv * Dh;
    }
}

// ---------------- gate (y * silu(z)) + RMSNorm; output tf32-rounded ----------------
__global__ __launch_bounds__(256) void gate_rms_k(const float* __restrict__ nw) {
    int row = blockIdx.x;
    const float* zp = g_proj + (size_t)row * PROJ_N;
    float* yp = g_y + (size_t)row * DSSMn;
    float ss = 0.f;
    for (int i = threadIdx.x; i < DSSMn; i += 256) {
        float z = zp[i];
        float gval = yp[i] * (z / (1.f + __expf(-z)));
        yp[i] = gval;
        ss += gval * gval;
    }
    ss = block_sum256(ss);
    float sc = rsqrtf(ss * (1.f/DSSMn) + EPSf);
    for (int i = threadIdx.x; i < DSSMn; i += 256)
        yp[i] = tf32r(yp[i] * sc * nw[i]);
}

// ---------------- combine: h = attn_h + ssm_h + residual ----------------
__global__ __launch_bounds__(256) void combine_k(const float* __restrict__ hidden) {
    int idx = blockIdx.x * blockDim.x + threadIdx.x;
    if (idx >= TOK*HIDn/4) return;
    float4 a = ((const float4*)g_attn_h)[idx];
    float4 s = ((const float4*)g_ssm_h)[idx];
    float4 r = ((const float4*)hidden)[idx];
    float4 o;
    o.x = a.x + s.x + r.x; o.y = a.y + s.y + r.y;
    o.z = a.z + s.z + r.z; o.w = a.w + s.w + r.w;
    ((float4*)g_h)[idx] = o;
}

// ---------------- MLP activation: silu(gate*0.9) * up; output tf32-rounded ----------------
__global__ __launch_bounds__(256) void act_k() {
    int idx = blockIdx.x * blockDim.x + threadIdx.x;
    if (idx >= TOK*INTERn) return;
    size_t row = (size_t)(idx / INTERn);
    int j = idx % INTERn;
    float gate = g_gu[row * (2*INTERn) + j] * GATE_MULT;
    float up   = g_gu[row * (2*INTERn) + INTERn + j];
    g_act[idx] = tf32r(gate / (1.f + __expf(-gate)) * up);
}

// ---------------- host launcher ----------------
static float* sym(const void* s) {
    void* p = nullptr;
    cudaGetSymbolAddress(&p, s);
    return (float*)p;
}

extern "C" void kernel_launch(void* const* d_in, const int* in_sizes, int n_in,
                              void* d_out, int out_size) {
    const float* hidden     = (const float*)d_in[0];
    const int*   positions  = (const int*)  d_in[1];
    const float* w_in_ln    = (const float*)d_in[2];
    const float* qkv_w      = (const float*)d_in[3];
    const float* o_w        = (const float*)d_in[4];
    const float* in_proj_w  = (const float*)d_in[5];
    const float* conv_w     = (const float*)d_in[6];
    const float* conv_b     = (const float*)d_in[7];
    const float* A_log      = (const float*)d_in[8];
    const float* dt_bias    = (const float*)d_in[9];
    const float* Dv         = (const float*)d_in[10];
    const float* ssm_norm_w = (const float*)d_in[11];
    const float* out_proj_w = (const float*)d_in[12];
    const float* w_pre_ff   = (const float*)d_in[13];
    const float* gate_up_w  = (const float*)d_in[14];
    const float* down_w     = (const float*)d_in[15];
    float* out = (float*)d_out;

    float* p_hs     = sym(g_hs);
    float* p_qkv    = sym(g_qkv);
    float* p_attn   = sym(g_attn);
    float* p_attn_h = sym(g_attn_h);
    float* p_proj   = sym(g_proj);
    float* p_y      = sym(g_y);
    float* p_ssm_h  = sym(g_ssm_h);
    float* p_h      = sym(g_h);
    float* p_h2     = sym(g_h2);
    float* p_gu     = sym(g_gu);
    float* p_act    = sym(g_act);
    float* p_wqkv   = sym(g_wqkv);
    float* p_wo     = sym(g_wo);
    float* p_win    = sym(g_win);
    float* p_wout   = sym(g_wout);
    float* p_wgu    = sym(g_wgu);
    float* p_wdn    = sym(g_wdn);

    // 0. tf32-round the weights
    {
        struct { const float* in; float* out; size_t n; } W[6] = {
            {qkv_w,     p_wqkv, (size_t)QKV_N*HIDn},
            {o_w,       p_wo,   (size_t)HIDn*HIDn},
            {in_proj_w, p_win,  (size_t)PROJ_N*HIDn},
            {out_proj_w,p_wout, (size_t)HIDn*DSSMn},
            {gate_up_w, p_wgu,  (size_t)2*INTERn*HIDn},
            {down_w,    p_wdn,  (size_t)HIDn*INTERn},
        };
        for (int i = 0; i < 6; i++) {
            int n4 = (int)(W[i].n / 4);
            cvtw_k<<<(n4 + 255)/256, 256>>>(W[i].in, W[i].out, n4);
        }
    }

    // 1. input RMSNorm (tf32-rounded output)
    rmsnorm_k<<<TOK, 256>>>(hidden, w_in_ln, p_hs);

    // 2. qkv projection (fold ATTN_IN)
    tgemm_nt<<<dim3(QKV_N/128, TOK/128), 256>>>(p_hs, p_wqkv, p_qkv, nullptr,
                                                TOK, QKV_N, HIDn, ATTN_IN);
    // 3. RoPE + key mult
    {
        int total = TOK * (NHn + NKVn) * (HDn/2);
        rope_k<<<(total + 255)/256, 256>>>(positions);
    }
    // 4. attention
    attn_k<<<dim3(Ln/32, Bn*NHn), 256>>>(p_qkv, p_attn);
    // 5. o projection (fold ATTN_OUT)
    tgemm_nt<<<dim3(HIDn/128, TOK/128), 256>>>(p_attn, p_wo, p_attn_h, nullptr,
                                               TOK, HIDn, HIDn, ATTN_OUT);

    // 6. SSM in_proj (fold SSM_IN)
    tgemm_nt<<<dim3((PROJ_N + 127)/128, TOK/128), 256>>>(p_hs, p_win, p_proj, nullptr,
                                                         TOK, PROJ_N, HIDn, SSM_IN);
    // 7. conv + silu ; dt softplus
    conv_k<<<(Bn*Ln*CONV_DIMn + 255)/256, 256>>>(conv_w, conv_b);
    dt_k<<<(TOK*MHn + 255)/256, 256>>>(dt_bias);
    // 8. selective scan
    scan_k<<<Bn*MHn, 512>>>(A_log, Dv);
    // 9. gate + RMS (tf32-rounded output)
    gate_rms_k<<<TOK, 256>>>(ssm_norm_w);
    // 10. out_proj (fold SSM_OUT)
    tgemm_nt<<<dim3(HIDn/128, TOK/128), 256>>>(p_y, p_wout, p_ssm_h, nullptr,
                                               TOK, HIDn, DSSMn, SSM_OUT);

    // 11. residual combine + pre-FF RMSNorm
    combine_k<<<(TOK*HIDn/4 + 255)/256, 256>>>(hidden);
    rmsnorm_k<<<TOK, 256>>>(p_h, w_pre_ff, p_h2);

    // 12. MLP
    tgemm_nt<<<dim3((2*INTERn)/128, TOK/128), 256>>>(p_h2, p_wgu, p_gu, nullptr,
                                                     TOK, 2*INTERn, HIDn, 1.0f);
    act_k<<<(TOK*INTERn + 255)/256, 256>>>();
    tgemm_nt<<<dim3(HIDn/128, TOK/128), 256>>>(p_act, p_wdn, out, p_h,
                                               TOK, HIDn, INTERn, DOWN_MULT);
}